// round 15
// baseline (speedup 1.0000x reference)
#include <cuda_runtime.h>
#include <cuda_fp16.h>
#include <cstdint>

#define N_NODES 20000
#define N_EDGES 320000

// ---------------- scratch ----------------
__device__ float  g_tmp [N_NODES * 128];
__device__ float  g_h1  [N_NODES * 128];
__device__ __half g_fsd [N_NODES * 512];
__device__ float  g_acc [N_NODES * 256];
__device__ float  g_s   [N_NODES * 2];
__device__ float  g_acc2[N_NODES * 256];
__device__ float  g_s2  [N_NODES * 2];
__device__ __half g_p   [N_NODES * 1024];
__device__ __half g_nw0h[128 * 64];
__device__ __half g_nw1h[128 * 128];
__device__ __half g_g1h [512 * 64];
__device__ __half g_g2h [512 * 256];
__device__ __half g_w0h [1024 * 384];
__device__ __half g_w1h [256 * 512];
__device__ float  g_b1cat[512], g_b2cat[512];

// ---------------- PTX helpers ----------------
__device__ __forceinline__ uint32_t smem_u32(const void* p) {
    uint32_t a;
    asm("{ .reg .u64 t; cvta.to.shared.u64 t, %1; cvt.u32.u64 %0, t; }" : "=r"(a) : "l"(p));
    return a;
}
__device__ __forceinline__ void ldm_x4(uint32_t* r, uint32_t a) {
    asm volatile("ldmatrix.sync.aligned.m8n8.x4.shared.b16 {%0,%1,%2,%3}, [%4];"
                 : "=r"(r[0]), "=r"(r[1]), "=r"(r[2]), "=r"(r[3]) : "r"(a));
}
__device__ __forceinline__ void mma_f32(float* c, const uint32_t* a, const uint32_t* b) {
    asm volatile("mma.sync.aligned.m16n8k16.row.col.f32.f16.f16.f32 "
                 "{%0,%1,%2,%3}, {%4,%5,%6,%7}, {%8,%9}, {%0,%1,%2,%3};"
                 : "+f"(c[0]), "+f"(c[1]), "+f"(c[2]), "+f"(c[3])
                 : "r"(a[0]), "r"(a[1]), "r"(a[2]), "r"(a[3]), "r"(b[0]), "r"(b[1]));
}
__device__ __forceinline__ void cp16(uint32_t d, const void* s) {
    asm volatile("cp.async.cg.shared.global [%0], [%1], 16;" :: "r"(d), "l"(s));
}
#define CP_COMMIT() asm volatile("cp.async.commit_group;")
#define CP_WAIT0()  asm volatile("cp.async.wait_group 0;")

// ================= node-side HMMA GEMM: single fp16, 512 threads, 2 CTAs/SM =================
// Kld = B row stride (halfs); K = reduction extent; A row stride = K.
// accum: epilogue adds into existing Ch (fp16) values.
__global__ void __launch_bounds__(512, 2)
mma_gemm_kernel(const float* __restrict__ A, int M, int K, int Kld,
                const __half* __restrict__ Bh,
                const float* __restrict__ bias, int in_relu, int out_relu,
                const float* __restrict__ rowscale,
                float* __restrict__ C, __half* __restrict__ Ch, int NTOT, int accum)
{
    extern __shared__ char smd[];
    const uint32_t sb = smem_u32(smd);
    const int tid  = threadIdx.x;
    const int lane = tid & 31;
    const int wid  = tid >> 5;
    const int wm   = wid >> 2;
    const int wn   = wid & 3;
    const int bm0  = blockIdx.y * 128;
    const int n0   = blockIdx.x * 128;
    const int ra   = tid >> 2;
    const int ua   = tid & 3;

    float acc[2][4][4];
#pragma unroll
    for (int a = 0; a < 2; a++)
#pragma unroll
        for (int b = 0; b < 4; b++)
#pragma unroll
            for (int c = 0; c < 4; c++) acc[a][b][c] = 0.f;

    const int NC = K >> 5;
    float apre[8];

    auto prefA = [&](int c) {
        const int kb = c * 32 + ua * 8;
        const int m = bm0 + ra;
        if (m < M) {
            const float4* p = reinterpret_cast<const float4*>(A + (size_t)m * K + kb);
#pragma unroll
            for (int i = 0; i < 2; i++) {
                float4 v = p[i];
                apre[i * 4 + 0] = v.x; apre[i * 4 + 1] = v.y;
                apre[i * 4 + 2] = v.z; apre[i * 4 + 3] = v.w;
            }
            if (rowscale != nullptr) {
                float sv = rowscale[m * 2 + (kb >= 128 ? 1 : 0)];
                float rs = (sv > 0.f) ? 1.f / sv : 0.f;
#pragma unroll
                for (int i = 0; i < 8; i++) apre[i] *= rs;
            }
            if (in_relu) {
#pragma unroll
                for (int i = 0; i < 8; i++) apre[i] = fmaxf(apre[i], 0.f);
            }
        } else {
#pragma unroll
            for (int i = 0; i < 8; i++) apre[i] = 0.f;
        }
    };

    auto storeA = [&](int s) {
        __half2 h2[4];
#pragma unroll
        for (int j = 0; j < 4; j++)
            h2[j] = __floats2half2_rn(apre[2 * j], apre[2 * j + 1]);
        *reinterpret_cast<uint4*>(smd + s * 20480 + ra * 80 + ua * 16) =
            *reinterpret_cast<uint4*>(h2);
    };

    auto cpB = [&](int c, int s) {
        const size_t go = (size_t)(n0 + ra) * Kld + c * 32 + ua * 8;
        cp16(sb + s * 20480 + 10240 + ra * 80 + ua * 16, Bh + go);
    };

    auto comp = [&](int s) {
        const uint32_t base = sb + s * 20480;
#pragma unroll
        for (int ks = 0; ks < 2; ks++) {
            uint32_t ah[2][4], bh[4][2];
            const uint32_t arow = wm * 32 + (lane & 15);
            const uint32_t au = ks * 2 + (lane >> 4);
#pragma unroll
            for (int mt = 0; mt < 2; mt++)
                ldm_x4(ah[mt], base + (arow + mt * 16) * 80 + au * 16);
            const uint32_t brow0 = wn * 32 + (lane & 7) + ((lane >> 4) << 3);
            const uint32_t bu = ks * 2 + ((lane >> 3) & 1);
#pragma unroll
            for (int pr = 0; pr < 2; pr++) {
                uint32_t t[4];
                ldm_x4(t, base + 10240 + (brow0 + pr * 16) * 80 + bu * 16);
                bh[2 * pr][0] = t[0]; bh[2 * pr][1] = t[1];
                bh[2 * pr + 1][0] = t[2]; bh[2 * pr + 1][1] = t[3];
            }
#pragma unroll
            for (int mt = 0; mt < 2; mt++)
#pragma unroll
                for (int nt = 0; nt < 4; nt++)
                    mma_f32(acc[mt][nt], ah[mt], bh[nt]);
        }
    };

    prefA(0); storeA(0); cpB(0, 0);
    CP_COMMIT(); CP_WAIT0();
    __syncthreads();

    for (int c = 0; c < NC; c++) {
        const int s = c & 1;
        if (c + 1 < NC) { prefA(c + 1); cpB(c + 1, s ^ 1); CP_COMMIT(); }
        comp(s);
        if (c + 1 < NC) { storeA(s ^ 1); CP_WAIT0(); }
        __syncthreads();
    }

#pragma unroll
    for (int mt = 0; mt < 2; mt++) {
        const int row = bm0 + wm * 32 + mt * 16 + (lane >> 2);
#pragma unroll
        for (int nt = 0; nt < 4; nt++) {
            const int col = n0 + wn * 32 + nt * 8 + 2 * (lane & 3);
            float b0 = bias ? bias[col] : 0.f;
            float b1 = bias ? bias[col + 1] : 0.f;
            float v0 = acc[mt][nt][0] + b0, v1 = acc[mt][nt][1] + b1;
            float v2 = acc[mt][nt][2] + b0, v3 = acc[mt][nt][3] + b1;
            if (out_relu) {
                v0 = fmaxf(v0, 0.f); v1 = fmaxf(v1, 0.f);
                v2 = fmaxf(v2, 0.f); v3 = fmaxf(v3, 0.f);
            }
            if (Ch) {
                __half2* p0 = reinterpret_cast<__half2*>(Ch + (size_t)row * NTOT + col);
                __half2* p1 = reinterpret_cast<__half2*>(Ch + (size_t)(row + 8) * NTOT + col);
                if (accum) {
                    if (row < M) {
                        float2 o = __half22float2(*p0);
                        *p0 = __floats2half2_rn(v0 + o.x, v1 + o.y);
                    }
                    if (row + 8 < M) {
                        float2 o = __half22float2(*p1);
                        *p1 = __floats2half2_rn(v2 + o.x, v3 + o.y);
                    }
                } else {
                    if (row < M)     *p0 = __floats2half2_rn(v0, v1);
                    if (row + 8 < M) *p1 = __floats2half2_rn(v2, v3);
                }
            } else {
                if (row < M)
                    *reinterpret_cast<float2*>(C + (size_t)row * NTOT + col) = make_float2(v0, v1);
                if (row + 8 < M)
                    *reinterpret_cast<float2*>(C + (size_t)(row + 8) * NTOT + col) = make_float2(v2, v3);
            }
        }
    }
}

// ================= edge HMMA kernel: BK=64 stages (8 iters), 512 threads =================
// stage (61440B): A0@0, A1@10240, B0@20480, B1@40960. 2 stages = 122880.
__global__ void __launch_bounds__(512)
edge_mma_kernel(const __half* __restrict__ P,
                const int* __restrict__ src, const int* __restrict__ dst,
                const float* __restrict__ eb0,
                const __half* __restrict__ Bh,
                const float* __restrict__ eb1, const float* __restrict__ ew2,
                const float* __restrict__ eb2, float* __restrict__ out)
{
    extern __shared__ char smd[];
    __shared__ float red[128];
    const uint32_t sb = smem_u32(smd);
    const int tid  = threadIdx.x;
    const int lane = tid & 31;
    const int wid  = tid >> 5;
    const int wm   = wid >> 2;
    const int wn   = wid & 3;
    const int e0   = blockIdx.x * 128;
    const int ra   = tid >> 2;        // A row 0..127
    const int ua   = tid & 3;         // 16-half segment within 64-k chunk
    const int rb   = tid >> 1;        // B row 0..255
    const int ubs  = tid & 1;         // B 32-half segment

    const int sn = src[e0 + ra];
    const int dn = dst[e0 + ra];
    if (tid < 128) red[tid] = 0.f;

    float acc[2][8][4];
#pragma unroll
    for (int a = 0; a < 2; a++)
#pragma unroll
        for (int b = 0; b < 8; b++)
#pragma unroll
            for (int c = 0; c < 4; c++) acc[a][b][c] = 0.f;

    __half2 apre[8];

    auto prefA = [&](int c) {
        const int kb = c * 64 + ua * 16;   // 16 contiguous halfs (32B)
        const __half2* ps = reinterpret_cast<const __half2*>(P + (size_t)sn * 1024 + kb);
        const __half2* pd = reinterpret_cast<const __half2*>(P + (size_t)dn * 1024 + 512 + kb);
        const float4* pb4 = reinterpret_cast<const float4*>(eb0 + kb);
        float bb[16];
#pragma unroll
        for (int i = 0; i < 4; i++) {
            float4 b = pb4[i];
            bb[4 * i] = b.x; bb[4 * i + 1] = b.y; bb[4 * i + 2] = b.z; bb[4 * i + 3] = b.w;
        }
#pragma unroll
        for (int i = 0; i < 8; i++) {
            float2 a2 = __half22float2(ps[i]);
            float2 d2 = __half22float2(pd[i]);
            float f0 = fmaxf(a2.x + d2.x + bb[2 * i], 0.f);
            float f1 = fmaxf(a2.y + d2.y + bb[2 * i + 1], 0.f);
            apre[i] = __floats2half2_rn(f0, f1);
        }
    };

    auto storeA = [&](int s) {
        // halfs [ua*16, ua*16+16): sub-chunk = ua>>1, offset within row = (ua&1)*32B
        char* dstp = smd + s * 61440 + (ua >> 1) * 10240 + ra * 80 + (ua & 1) * 32;
        *reinterpret_cast<uint4*>(dstp)      = *reinterpret_cast<uint4*>(apre);
        *reinterpret_cast<uint4*>(dstp + 16) = *reinterpret_cast<uint4*>(apre + 4);
    };

    auto cpB = [&](int c, int s) {
        // thread's 64B: rows rb, halfs [c*64 + ubs*32, +32): all in sub-chunk ubs
        const __half* g = Bh + (size_t)rb * 512 + c * 64 + ubs * 32;
        const uint32_t d = sb + s * 61440 + 20480 + ubs * 20480 + rb * 80;
#pragma unroll
        for (int u = 0; u < 4; u++)
            cp16(d + u * 16, g + u * 8);
    };

    auto comp = [&](int s) {
        const uint32_t stage = sb + s * 61440;
#pragma unroll
        for (int sub = 0; sub < 2; sub++) {
            const uint32_t abase = stage + sub * 10240;
            const uint32_t bbase = stage + 20480 + sub * 20480;
#pragma unroll
            for (int ks = 0; ks < 2; ks++) {
                uint32_t ah[2][4], bh[8][2];
                const uint32_t arow = wm * 32 + (lane & 15);
                const uint32_t au = ks * 2 + (lane >> 4);
#pragma unroll
                for (int mt = 0; mt < 2; mt++)
                    ldm_x4(ah[mt], abase + (arow + mt * 16) * 80 + au * 16);
                const uint32_t brow0 = wn * 64 + (lane & 7) + ((lane >> 4) << 3);
                const uint32_t bu = ks * 2 + ((lane >> 3) & 1);
#pragma unroll
                for (int pr = 0; pr < 4; pr++) {
                    uint32_t t[4];
                    ldm_x4(t, bbase + (brow0 + pr * 16) * 80 + bu * 16);
                    bh[2 * pr][0] = t[0]; bh[2 * pr][1] = t[1];
                    bh[2 * pr + 1][0] = t[2]; bh[2 * pr + 1][1] = t[3];
                }
#pragma unroll
                for (int mt = 0; mt < 2; mt++)
#pragma unroll
                    for (int nt = 0; nt < 8; nt++)
                        mma_f32(acc[mt][nt], ah[mt], bh[nt]);
            }
        }
    };

    prefA(0); storeA(0); cpB(0, 0);
    CP_COMMIT(); CP_WAIT0();
    __syncthreads();

#pragma unroll 1
    for (int c = 0; c < 8; c++) {
        const int s = c & 1;
        if (c + 1 < 8) { prefA(c + 1); cpB(c + 1, s ^ 1); CP_COMMIT(); }
        comp(s);
        if (c + 1 < 8) { storeA(s ^ 1); CP_WAIT0(); }
        __syncthreads();
    }

#pragma unroll
    for (int mt = 0; mt < 2; mt++) {
        float p0 = 0.f, p1 = 0.f;
#pragma unroll
        for (int nt = 0; nt < 8; nt++) {
            const int col = wn * 64 + nt * 8 + 2 * (lane & 3);
            const float b0 = eb1[col], b1 = eb1[col + 1];
            const float w0 = ew2[col], w1 = ew2[col + 1];
            p0 += fmaxf(acc[mt][nt][0] + b0, 0.f) * w0 + fmaxf(acc[mt][nt][1] + b1, 0.f) * w1;
            p1 += fmaxf(acc[mt][nt][2] + b0, 0.f) * w0 + fmaxf(acc[mt][nt][3] + b1, 0.f) * w1;
        }
        p0 += __shfl_xor_sync(0xffffffffu, p0, 1);
        p0 += __shfl_xor_sync(0xffffffffu, p0, 2);
        p1 += __shfl_xor_sync(0xffffffffu, p1, 1);
        p1 += __shfl_xor_sync(0xffffffffu, p1, 2);
        if ((lane & 3) == 0) {
            atomicAdd(&red[wm * 32 + mt * 16 + (lane >> 2)], p0);
            atomicAdd(&red[wm * 32 + mt * 16 + (lane >> 2) + 8], p1);
        }
    }
    __syncthreads();
    if (tid < 128) out[e0 + tid] = red[tid] + eb2[0];
}

// ================= GAT fused pass (round-9 proven) =================
__global__ void gat_fused_kernel(const __half* __restrict__ fsd,
                                 const float* __restrict__ attn,
                                 const int* __restrict__ src, const int* __restrict__ dst,
                                 float* __restrict__ s, float* __restrict__ acc)
{
    int e = (blockIdx.x * blockDim.x + threadIdx.x) >> 5;
    int lane = threadIdx.x & 31;
    if (e >= N_EDGES) return;
    int sN = src[e], tN = dst[e];
#pragma unroll
    for (int h = 0; h < 2; h++) {
        const __half2* pa = reinterpret_cast<const __half2*>(fsd + (size_t)sN * 512 + h * 128 + lane * 4);
        const __half2* pb = reinterpret_cast<const __half2*>(fsd + (size_t)tN * 512 + 256 + h * 128 + lane * 4);
        float2 a0 = __half22float2(pa[0]), a1 = __half22float2(pa[1]);
        float2 b0 = __half22float2(pb[0]), b1 = __half22float2(pb[1]);
        float4 t = *reinterpret_cast<const float4*>(attn + h * 128 + lane * 4);
        float v0 = a0.x + b0.x, v1 = a0.y + b0.y, v2 = a1.x + b1.x, v3 = a1.y + b1.y;
        v0 = (v0 > 0.f) ? v0 : 0.2f * v0;
        v1 = (v1 > 0.f) ? v1 : 0.2f * v1;
        v2 = (v2 > 0.f) ? v2 : 0.2f * v2;
        v3 = (v3 > 0.f) ? v3 : 0.2f * v3;
        float lg = v0 * t.x + v1 * t.y + v2 * t.z + v3 * t.w;
#pragma unroll
        for (int o = 16; o; o >>= 1) lg += __shfl_xor_sync(0xffffffffu, lg, o);
        float ev = expf(lg);
        if (lane == 0) atomicAdd(&s[tN * 2 + h], ev);
        float4 v = make_float4(a0.x * ev, a0.y * ev, a1.x * ev, a1.y * ev);
        atomicAdd(reinterpret_cast<float4*>(acc + (size_t)tN * 256 + h * 128 + lane * 4), v);
    }
}

// ================= fused prep kernel (proven) =================
__device__ __forceinline__ void split_at(const float* W, __half* th, int K, int N, int i)
{
    int n = i / K, k = i % K;
    th[i] = __float2half_rn(W[(size_t)k * N + n]);
}

__global__ void prep_kernel(const float* nw0, const float* nw1,
                            const float* g1ws, const float* g1wd,
                            const float* g2ws, const float* g2wd,
                            const float* ew0, const float* ew1,
                            const float* g1bs, const float* g1bd,
                            const float* g2bs, const float* g2bd,
                            __half* nw0h, __half* nw1h,
                            __half* g1h, __half* g2h,
                            __half* w0h, __half* w1h,
                            float* b1c, float* b2c)
{
    int i = blockIdx.x * blockDim.x + threadIdx.x;
    if (i < 8192) { split_at(nw0, nw0h, 64, 128, i); return; }
    i -= 8192;
    if (i < 16384) { split_at(nw1, nw1h, 128, 128, i); return; }
    i -= 16384;
    if (i < 16384) { split_at(g1ws, g1h, 64, 256, i); return; }
    i -= 16384;
    if (i < 16384) { split_at(g1wd, g1h + 16384, 64, 256, i); return; }
    i -= 16384;
    if (i < 65536) { split_at(g2ws, g2h, 256, 256, i); return; }
    i -= 65536;
    if (i < 65536) { split_at(g2wd, g2h + 65536, 256, 256, i); return; }
    i -= 65536;
    if (i < 196608) {
        int n = i / 384, k = i % 384;
        int rs = (k < 128) ? k : k + 128;
        int rd = (k < 128) ? k + 128 : k + 384;
        w0h[i] = __float2half_rn(ew0[rs * 512 + n]);
        w0h[196608 + i] = __float2half_rn(ew0[rd * 512 + n]);
        return;
    }
    i -= 196608;
    if (i < 131072) { split_at(ew1, w1h, 512, 256, i); return; }
    i -= 131072;
    if (i < 512) { b1c[i] = (i < 256) ? g1bs[i] : g1bd[i - 256]; return; }
    i -= 512;
    if (i < 512) { b2c[i] = (i < 256) ? g2bs[i] : g2bd[i - 256]; return; }
}

// ---------------- host launch (fork-join; P1 overlapped) ----------------
extern "C" void kernel_launch(void* const* d_in, const int* in_sizes, int n_in,
                              void* d_out, int out_size)
{
    const float* x    = (const float*)d_in[0];
    const int*   src  = (const int*)d_in[1];
    const int*   dst  = (const int*)d_in[2];
    const float* nw0  = (const float*)d_in[3];
    const float* nb0  = (const float*)d_in[4];
    const float* nw1  = (const float*)d_in[5];
    const float* nb1  = (const float*)d_in[6];
    const float* g1ws = (const float*)d_in[7];
    const float* g1bs = (const float*)d_in[8];
    const float* g1wd = (const float*)d_in[9];
    const float* g1bd = (const float*)d_in[10];
    const float* g1a  = (const float*)d_in[11];
    const float* g2ws = (const float*)d_in[12];
    const float* g2bs = (const float*)d_in[13];
    const float* g2wd = (const float*)d_in[14];
    const float* g2bd = (const float*)d_in[15];
    const float* g2a  = (const float*)d_in[16];
    const float* ew0  = (const float*)d_in[17];
    const float* eb0  = (const float*)d_in[18];
    const float* ew1  = (const float*)d_in[19];
    const float* eb1  = (const float*)d_in[20];
    const float* ew2  = (const float*)d_in[21];
    const float* eb2  = (const float*)d_in[22];
    float* out = (float*)d_out;

    float *tmp, *h1, *acc, *sB, *acc2, *s2B, *b1c, *b2c;
    __half *fsd, *P;
    __half *nw0h, *nw1h, *g1h, *g2h, *w0h, *w1h;
    cudaGetSymbolAddress((void**)&tmp,  g_tmp);
    cudaGetSymbolAddress((void**)&h1,   g_h1);
    cudaGetSymbolAddress((void**)&fsd,  g_fsd);
    cudaGetSymbolAddress((void**)&acc,  g_acc);
    cudaGetSymbolAddress((void**)&sB,   g_s);
    cudaGetSymbolAddress((void**)&acc2, g_acc2);
    cudaGetSymbolAddress((void**)&s2B,  g_s2);
    cudaGetSymbolAddress((void**)&P,    g_p);
    cudaGetSymbolAddress((void**)&b1c,  g_b1cat);
    cudaGetSymbolAddress((void**)&b2c,  g_b2cat);
    cudaGetSymbolAddress((void**)&nw0h, g_nw0h);
    cudaGetSymbolAddress((void**)&nw1h, g_nw1h);
    cudaGetSymbolAddress((void**)&g1h,  g_g1h);
    cudaGetSymbolAddress((void**)&g2h,  g_g2h);
    cudaGetSymbolAddress((void**)&w0h,  g_w0h);
    cudaGetSymbolAddress((void**)&w1h,  g_w1h);

    cudaFuncSetAttribute(mma_gemm_kernel, cudaFuncAttributeMaxDynamicSharedMemorySize, 40960);
    cudaFuncSetAttribute(edge_mma_kernel, cudaFuncAttributeMaxDynamicSharedMemorySize, 122880);

    cudaStream_t s2;
    cudaEvent_t eFork, eMs, eJoin;
    cudaStreamCreateWithFlags(&s2, cudaStreamNonBlocking);
    cudaEventCreateWithFlags(&eFork, cudaEventDisableTiming);
    cudaEventCreateWithFlags(&eMs,   cudaEventDisableTiming);
    cudaEventCreateWithFlags(&eJoin, cudaEventDisableTiming);

    const int MBY = (N_NODES + 127) / 128;   // 157

    // main: prep, then fork
    prep_kernel<<<(517120 + 255) / 256, 256>>>(
        nw0, nw1, g1ws, g1wd, g2ws, g2wd, ew0, ew1,
        g1bs, g1bd, g2bs, g2bd,
        nw0h, nw1h, g1h, g2h, w0h, w1h, b1c, b2c);
    cudaEventRecord(eFork, 0);
    cudaStreamWaitEvent(s2, eFork, 0);

    // side stream: memsets, NodeMLP, then P1 = h1 @ W0[k<128]
    cudaMemsetAsync(acc,  0, (size_t)N_NODES * 256 * sizeof(float), s2);
    cudaMemsetAsync(sB,   0, (size_t)N_NODES * 2 * sizeof(float), s2);
    cudaMemsetAsync(acc2, 0, (size_t)N_NODES * 256 * sizeof(float), s2);
    cudaMemsetAsync(s2B,  0, (size_t)N_NODES * 2 * sizeof(float), s2);
    cudaEventRecord(eMs, s2);
    mma_gemm_kernel<<<dim3(1, MBY), 512, 40960, s2>>>(
        x, N_NODES, 64, 64, nw0h, nb0, 0, 1, nullptr, tmp, nullptr, 128, 0);
    mma_gemm_kernel<<<dim3(1, MBY), 512, 40960, s2>>>(
        tmp, N_NODES, 128, 128, nw1h, nb1, 0, 1, nullptr, h1, nullptr, 128, 0);
    mma_gemm_kernel<<<dim3(8, MBY), 512, 40960, s2>>>(
        h1, N_NODES, 128, 384, w0h, nullptr, 0, 0, nullptr, nullptr, P, 1024, 0);
    cudaEventRecord(eJoin, s2);

    // main: GAT critical chain
    mma_gemm_kernel<<<dim3(4, MBY), 512, 40960>>>(
        x, N_NODES, 64, 64, g1h, b1c, 0, 0, nullptr, nullptr, fsd, 512, 0);
    cudaStreamWaitEvent(0, eMs, 0);
    gat_fused_kernel<<<N_EDGES / 8, 256>>>(fsd, g1a, src, dst, sB, acc);

    mma_gemm_kernel<<<dim3(4, MBY), 512, 40960>>>(
        acc, N_NODES, 256, 256, g2h, b2c, 1, 0, sB, nullptr, fsd, 512, 0);
    gat_fused_kernel<<<N_EDGES / 8, 256>>>(fsd, g2a, src, dst, s2B, acc2);

    // join; P2 = relu(acc2/s2) @ W0[k>=128], accumulating into P
    cudaStreamWaitEvent(0, eJoin, 0);
    mma_gemm_kernel<<<dim3(8, MBY), 512, 40960>>>(
        acc2, N_NODES, 256, 384, w0h + 128, nullptr, 1, 0, s2B, nullptr, P, 1024, 1);

    // EdgeMLP fused (BK=64)
    edge_mma_kernel<<<N_EDGES / 128, 512, 122880>>>(
        P, src, dst, eb0, w1h, eb1, ew2, eb2, out);

    cudaStreamDestroy(s2);
    cudaEventDestroy(eFork);
    cudaEventDestroy(eMs);
    cudaEventDestroy(eJoin);
}

// round 16
// speedup vs baseline: 1.1145x; 1.1145x over previous
#include <cuda_runtime.h>
#include <cuda_fp16.h>
#include <cstdint>

#define N_NODES 20000
#define N_EDGES 320000

// ---------------- scratch ----------------
__device__ float  g_tmp [N_NODES * 128];
__device__ float  g_h1  [N_NODES * 128];
__device__ __half g_fsd [N_NODES * 512];
__device__ float  g_acc [N_NODES * 256];
__device__ float  g_s   [N_NODES * 2];
__device__ float  g_acc2[N_NODES * 256];
__device__ float  g_s2  [N_NODES * 2];
__device__ __half g_p   [N_NODES * 1024];
__device__ int    g_cnt   [N_NODES];
__device__ int    g_cursor[N_NODES];
__device__ int    g_esrc  [N_EDGES];
__device__ int    g_edst  [N_EDGES];
__device__ int    g_eidx  [N_EDGES];
__device__ __half g_nw0h[128 * 64];
__device__ __half g_nw1h[128 * 128];
__device__ __half g_g1h [512 * 64];
__device__ __half g_g2h [512 * 256];
__device__ __half g_w0h [1024 * 384];
__device__ __half g_w1h [256 * 512];
__device__ float  g_b1cat[512], g_b2cat[512];

// ---------------- PTX helpers ----------------
__device__ __forceinline__ uint32_t smem_u32(const void* p) {
    uint32_t a;
    asm("{ .reg .u64 t; cvta.to.shared.u64 t, %1; cvt.u32.u64 %0, t; }" : "=r"(a) : "l"(p));
    return a;
}
__device__ __forceinline__ void ldm_x4(uint32_t* r, uint32_t a) {
    asm volatile("ldmatrix.sync.aligned.m8n8.x4.shared.b16 {%0,%1,%2,%3}, [%4];"
                 : "=r"(r[0]), "=r"(r[1]), "=r"(r[2]), "=r"(r[3]) : "r"(a));
}
__device__ __forceinline__ void mma_f32(float* c, const uint32_t* a, const uint32_t* b) {
    asm volatile("mma.sync.aligned.m16n8k16.row.col.f32.f16.f16.f32 "
                 "{%0,%1,%2,%3}, {%4,%5,%6,%7}, {%8,%9}, {%0,%1,%2,%3};"
                 : "+f"(c[0]), "+f"(c[1]), "+f"(c[2]), "+f"(c[3])
                 : "r"(a[0]), "r"(a[1]), "r"(a[2]), "r"(a[3]), "r"(b[0]), "r"(b[1]));
}
__device__ __forceinline__ void cp16(uint32_t d, const void* s) {
    asm volatile("cp.async.cg.shared.global [%0], [%1], 16;" :: "r"(d), "l"(s));
}
#define CP_COMMIT() asm volatile("cp.async.commit_group;")
#define CP_WAIT0()  asm volatile("cp.async.wait_group 0;")

// ================= node-side HMMA GEMM (round-14 proven) =================
__global__ void __launch_bounds__(512, 2)
mma_gemm_kernel(const float* __restrict__ A, int M, int K,
                const float* __restrict__ A2,
                const __half* __restrict__ Bh,
                const float* __restrict__ bias, int in_relu, int out_relu,
                const float* __restrict__ rowscale,
                float* __restrict__ C, __half* __restrict__ Ch, int NTOT)
{
    extern __shared__ char smd[];
    const uint32_t sb = smem_u32(smd);
    const int tid  = threadIdx.x;
    const int lane = tid & 31;
    const int wid  = tid >> 5;
    const int wm   = wid >> 2;
    const int wn   = wid & 3;
    const int bm0  = blockIdx.y * 128;
    const int n0   = blockIdx.x * 128;
    const int ra   = tid >> 2;
    const int ua   = tid & 3;

    float acc[2][4][4];
#pragma unroll
    for (int a = 0; a < 2; a++)
#pragma unroll
        for (int b = 0; b < 4; b++)
#pragma unroll
            for (int c = 0; c < 4; c++) acc[a][b][c] = 0.f;

    const int NC = K >> 5;
    float apre[8];

    auto prefA = [&](int c) {
        const int kb = c * 32 + ua * 8;
        const int m = bm0 + ra;
        if (m < M) {
            if (A2 != nullptr && kb >= 128) {
                const int q = kb - 128;
                const float4* p = reinterpret_cast<const float4*>(A2 + (size_t)m * 256 + q);
#pragma unroll
                for (int i = 0; i < 2; i++) {
                    float4 v = p[i];
                    apre[i * 4 + 0] = v.x; apre[i * 4 + 1] = v.y;
                    apre[i * 4 + 2] = v.z; apre[i * 4 + 3] = v.w;
                }
                float sv = rowscale[m * 2 + (q >= 128 ? 1 : 0)];
                float rs = (sv > 0.f) ? 1.f / sv : 0.f;
#pragma unroll
                for (int i = 0; i < 8; i++) apre[i] = fmaxf(apre[i] * rs, 0.f);
            } else {
                const int stride = (A2 != nullptr) ? 128 : K;
                const float4* p = reinterpret_cast<const float4*>(A + (size_t)m * stride + kb);
#pragma unroll
                for (int i = 0; i < 2; i++) {
                    float4 v = p[i];
                    apre[i * 4 + 0] = v.x; apre[i * 4 + 1] = v.y;
                    apre[i * 4 + 2] = v.z; apre[i * 4 + 3] = v.w;
                }
                if (A2 == nullptr && rowscale != nullptr) {
                    float sv = rowscale[m * 2 + (kb >= 128 ? 1 : 0)];
                    float rs = (sv > 0.f) ? 1.f / sv : 0.f;
#pragma unroll
                    for (int i = 0; i < 8; i++) apre[i] *= rs;
                }
                if (in_relu) {
#pragma unroll
                    for (int i = 0; i < 8; i++) apre[i] = fmaxf(apre[i], 0.f);
                }
            }
        } else {
#pragma unroll
            for (int i = 0; i < 8; i++) apre[i] = 0.f;
        }
    };

    auto storeA = [&](int s) {
        __half2 h2[4];
#pragma unroll
        for (int j = 0; j < 4; j++)
            h2[j] = __floats2half2_rn(apre[2 * j], apre[2 * j + 1]);
        *reinterpret_cast<uint4*>(smd + s * 20480 + ra * 80 + ua * 16) =
            *reinterpret_cast<uint4*>(h2);
    };

    auto cpB = [&](int c, int s) {
        const size_t go = (size_t)(n0 + ra) * K + c * 32 + ua * 8;
        cp16(sb + s * 20480 + 10240 + ra * 80 + ua * 16, Bh + go);
    };

    auto comp = [&](int s) {
        const uint32_t base = sb + s * 20480;
#pragma unroll
        for (int ks = 0; ks < 2; ks++) {
            uint32_t ah[2][4], bh[4][2];
            const uint32_t arow = wm * 32 + (lane & 15);
            const uint32_t au = ks * 2 + (lane >> 4);
#pragma unroll
            for (int mt = 0; mt < 2; mt++)
                ldm_x4(ah[mt], base + (arow + mt * 16) * 80 + au * 16);
            const uint32_t brow0 = wn * 32 + (lane & 7) + ((lane >> 4) << 3);
            const uint32_t bu = ks * 2 + ((lane >> 3) & 1);
#pragma unroll
            for (int pr = 0; pr < 2; pr++) {
                uint32_t t[4];
                ldm_x4(t, base + 10240 + (brow0 + pr * 16) * 80 + bu * 16);
                bh[2 * pr][0] = t[0]; bh[2 * pr][1] = t[1];
                bh[2 * pr + 1][0] = t[2]; bh[2 * pr + 1][1] = t[3];
            }
#pragma unroll
            for (int mt = 0; mt < 2; mt++)
#pragma unroll
                for (int nt = 0; nt < 4; nt++)
                    mma_f32(acc[mt][nt], ah[mt], bh[nt]);
        }
    };

    prefA(0); storeA(0); cpB(0, 0);
    CP_COMMIT(); CP_WAIT0();
    __syncthreads();

    for (int c = 0; c < NC; c++) {
        const int s = c & 1;
        if (c + 1 < NC) { prefA(c + 1); cpB(c + 1, s ^ 1); CP_COMMIT(); }
        comp(s);
        if (c + 1 < NC) { storeA(s ^ 1); CP_WAIT0(); }
        __syncthreads();
    }

#pragma unroll
    for (int mt = 0; mt < 2; mt++) {
        const int row = bm0 + wm * 32 + mt * 16 + (lane >> 2);
#pragma unroll
        for (int nt = 0; nt < 4; nt++) {
            const int col = n0 + wn * 32 + nt * 8 + 2 * (lane & 3);
            float b0 = bias ? bias[col] : 0.f;
            float b1 = bias ? bias[col + 1] : 0.f;
            float v0 = acc[mt][nt][0] + b0, v1 = acc[mt][nt][1] + b1;
            float v2 = acc[mt][nt][2] + b0, v3 = acc[mt][nt][3] + b1;
            if (out_relu) {
                v0 = fmaxf(v0, 0.f); v1 = fmaxf(v1, 0.f);
                v2 = fmaxf(v2, 0.f); v3 = fmaxf(v3, 0.f);
            }
            if (Ch) {
                if (row < M)
                    *reinterpret_cast<__half2*>(Ch + (size_t)row * NTOT + col) =
                        __floats2half2_rn(v0, v1);
                if (row + 8 < M)
                    *reinterpret_cast<__half2*>(Ch + (size_t)(row + 8) * NTOT + col) =
                        __floats2half2_rn(v2, v3);
            } else {
                if (row < M)
                    *reinterpret_cast<float2*>(C + (size_t)row * NTOT + col) = make_float2(v0, v1);
                if (row + 8 < M)
                    *reinterpret_cast<float2*>(C + (size_t)(row + 8) * NTOT + col) = make_float2(v2, v3);
            }
        }
    }
}

// ================= edge HMMA kernel: round-9 form, dst-sorted edge order =================
__global__ void __launch_bounds__(512)
edge_mma_kernel(const __half* __restrict__ P,
                const int* __restrict__ esrc, const int* __restrict__ edst,
                const int* __restrict__ eidx,
                const float* __restrict__ eb0,
                const __half* __restrict__ Bh,
                const float* __restrict__ eb1, const float* __restrict__ ew2,
                const float* __restrict__ eb2, float* __restrict__ out)
{
    extern __shared__ char smd[];
    __shared__ float red[128];
    const uint32_t sb = smem_u32(smd);
    const int tid  = threadIdx.x;
    const int lane = tid & 31;
    const int wid  = tid >> 5;
    const int wm   = wid >> 2;
    const int wn   = wid & 3;
    const int e0   = blockIdx.x * 128;
    const int ra   = tid >> 2;
    const int ua   = tid & 3;
    const int rb   = tid >> 1;
    const int ub   = (tid & 1) * 2;

    const int sn = esrc[e0 + ra];
    const int dn = edst[e0 + ra];
    if (tid < 128) red[tid] = 0.f;

    float acc[2][8][4];
#pragma unroll
    for (int a = 0; a < 2; a++)
#pragma unroll
        for (int b = 0; b < 8; b++)
#pragma unroll
            for (int c = 0; c < 4; c++) acc[a][b][c] = 0.f;

    __half2 apre[4];

    auto prefA = [&](int c) {
        const int kb = c * 32 + ua * 8;
        const __half2* ps = reinterpret_cast<const __half2*>(P + (size_t)sn * 1024 + kb);
        const __half2* pd = reinterpret_cast<const __half2*>(P + (size_t)dn * 1024 + 512 + kb);
        const float4* pb4 = reinterpret_cast<const float4*>(eb0 + kb);
        float4 b0 = pb4[0], b1 = pb4[1];
        float bb[8] = {b0.x, b0.y, b0.z, b0.w, b1.x, b1.y, b1.z, b1.w};
#pragma unroll
        for (int i = 0; i < 4; i++) {
            float2 a2 = __half22float2(ps[i]);
            float2 d2 = __half22float2(pd[i]);
            float f0 = fmaxf(a2.x + d2.x + bb[2 * i], 0.f);
            float f1 = fmaxf(a2.y + d2.y + bb[2 * i + 1], 0.f);
            apre[i] = __floats2half2_rn(f0, f1);
        }
    };

    auto storeA = [&](int s) {
        *reinterpret_cast<uint4*>(smd + s * 30720 + ra * 80 + ua * 16) =
            *reinterpret_cast<uint4*>(apre);
    };

    auto cpB = [&](int c, int s) {
        const size_t go = (size_t)rb * 512 + c * 32;
        const uint32_t db = sb + s * 30720 + 10240 + rb * 80;
#pragma unroll
        for (int u = 0; u < 2; u++)
            cp16(db + (ub + u) * 16, Bh + go + (ub + u) * 8);
    };

    auto comp = [&](int s) {
        const uint32_t base = sb + s * 30720;
#pragma unroll
        for (int ks = 0; ks < 2; ks++) {
            uint32_t ah[2][4], bh[8][2];
            const uint32_t arow = wm * 32 + (lane & 15);
            const uint32_t au = ks * 2 + (lane >> 4);
#pragma unroll
            for (int mt = 0; mt < 2; mt++)
                ldm_x4(ah[mt], base + (arow + mt * 16) * 80 + au * 16);
            const uint32_t brow0 = wn * 64 + (lane & 7) + ((lane >> 4) << 3);
            const uint32_t bu = ks * 2 + ((lane >> 3) & 1);
#pragma unroll
            for (int pr = 0; pr < 4; pr++) {
                uint32_t t[4];
                ldm_x4(t, base + 10240 + (brow0 + pr * 16) * 80 + bu * 16);
                bh[2 * pr][0] = t[0]; bh[2 * pr][1] = t[1];
                bh[2 * pr + 1][0] = t[2]; bh[2 * pr + 1][1] = t[3];
            }
#pragma unroll
            for (int mt = 0; mt < 2; mt++)
#pragma unroll
                for (int nt = 0; nt < 8; nt++)
                    mma_f32(acc[mt][nt], ah[mt], bh[nt]);
        }
    };

    prefA(0); storeA(0); cpB(0, 0);
    CP_COMMIT(); CP_WAIT0();
    __syncthreads();

#pragma unroll 1
    for (int c = 0; c < 16; c++) {
        const int s = c & 1;
        if (c + 1 < 16) { prefA(c + 1); cpB(c + 1, s ^ 1); CP_COMMIT(); }
        comp(s);
        if (c + 1 < 16) { storeA(s ^ 1); CP_WAIT0(); }
        __syncthreads();
    }

#pragma unroll
    for (int mt = 0; mt < 2; mt++) {
        float p0 = 0.f, p1 = 0.f;
#pragma unroll
        for (int nt = 0; nt < 8; nt++) {
            const int col = wn * 64 + nt * 8 + 2 * (lane & 3);
            const float b0 = eb1[col], b1 = eb1[col + 1];
            const float w0 = ew2[col], w1 = ew2[col + 1];
            p0 += fmaxf(acc[mt][nt][0] + b0, 0.f) * w0 + fmaxf(acc[mt][nt][1] + b1, 0.f) * w1;
            p1 += fmaxf(acc[mt][nt][2] + b0, 0.f) * w0 + fmaxf(acc[mt][nt][3] + b1, 0.f) * w1;
        }
        p0 += __shfl_xor_sync(0xffffffffu, p0, 1);
        p0 += __shfl_xor_sync(0xffffffffu, p0, 2);
        p1 += __shfl_xor_sync(0xffffffffu, p1, 1);
        p1 += __shfl_xor_sync(0xffffffffu, p1, 2);
        if ((lane & 3) == 0) {
            atomicAdd(&red[wm * 32 + mt * 16 + (lane >> 2)], p0);
            atomicAdd(&red[wm * 32 + mt * 16 + (lane >> 2) + 8], p1);
        }
    }
    __syncthreads();
    if (tid < 128) out[eidx[e0 + tid]] = red[tid] + eb2[0];
}

// ================= CSR build (side stream; dst-sorted edge order) =================
__global__ void csr_hist_kernel(const int* __restrict__ dst, int* __restrict__ cnt)
{
    int e = blockIdx.x * blockDim.x + threadIdx.x;
    if (e < N_EDGES) atomicAdd(&cnt[dst[e]], 1);
}

__global__ void __launch_bounds__(1024)
csr_scan_kernel(const int* __restrict__ cnt, int* __restrict__ cursor)
{
    __shared__ int sums[1024];
    __shared__ int offs[1024];
    const int t = threadIdx.x;
    const int CH = (N_NODES + 1023) / 1024;
    const int base = t * CH;
    int s = 0;
    for (int i = 0; i < CH; i++) {
        int idx = base + i;
        if (idx < N_NODES) s += cnt[idx];
    }
    sums[t] = s;
    __syncthreads();
    if (t == 0) {
        int run = 0;
        for (int i = 0; i < 1024; i++) { offs[i] = run; run += sums[i]; }
    }
    __syncthreads();
    int run = offs[t];
    for (int i = 0; i < CH; i++) {
        int idx = base + i;
        if (idx < N_NODES) { cursor[idx] = run; run += cnt[idx]; }
    }
}

__global__ void csr_fill_kernel(const int* __restrict__ src, const int* __restrict__ dst,
                                int* __restrict__ cursor,
                                int* __restrict__ esrc, int* __restrict__ edst,
                                int* __restrict__ eidx)
{
    int e = blockIdx.x * blockDim.x + threadIdx.x;
    if (e >= N_EDGES) return;
    int d = dst[e];
    int p = atomicAdd(&cursor[d], 1);
    esrc[p] = src[e];
    edst[p] = d;
    eidx[p] = e;
}

// ================= GAT fused pass (round-9 proven) =================
__global__ void gat_fused_kernel(const __half* __restrict__ fsd,
                                 const float* __restrict__ attn,
                                 const int* __restrict__ src, const int* __restrict__ dst,
                                 float* __restrict__ s, float* __restrict__ acc)
{
    int e = (blockIdx.x * blockDim.x + threadIdx.x) >> 5;
    int lane = threadIdx.x & 31;
    if (e >= N_EDGES) return;
    int sN = src[e], tN = dst[e];
#pragma unroll
    for (int h = 0; h < 2; h++) {
        const __half2* pa = reinterpret_cast<const __half2*>(fsd + (size_t)sN * 512 + h * 128 + lane * 4);
        const __half2* pb = reinterpret_cast<const __half2*>(fsd + (size_t)tN * 512 + 256 + h * 128 + lane * 4);
        float2 a0 = __half22float2(pa[0]), a1 = __half22float2(pa[1]);
        float2 b0 = __half22float2(pb[0]), b1 = __half22float2(pb[1]);
        float4 t = *reinterpret_cast<const float4*>(attn + h * 128 + lane * 4);
        float v0 = a0.x + b0.x, v1 = a0.y + b0.y, v2 = a1.x + b1.x, v3 = a1.y + b1.y;
        v0 = (v0 > 0.f) ? v0 : 0.2f * v0;
        v1 = (v1 > 0.f) ? v1 : 0.2f * v1;
        v2 = (v2 > 0.f) ? v2 : 0.2f * v2;
        v3 = (v3 > 0.f) ? v3 : 0.2f * v3;
        float lg = v0 * t.x + v1 * t.y + v2 * t.z + v3 * t.w;
#pragma unroll
        for (int o = 16; o; o >>= 1) lg += __shfl_xor_sync(0xffffffffu, lg, o);
        float ev = expf(lg);
        if (lane == 0) atomicAdd(&s[tN * 2 + h], ev);
        float4 v = make_float4(a0.x * ev, a0.y * ev, a1.x * ev, a1.y * ev);
        atomicAdd(reinterpret_cast<float4*>(acc + (size_t)tN * 256 + h * 128 + lane * 4), v);
    }
}

// ================= fused prep kernel (proven) =================
__device__ __forceinline__ void split_at(const float* W, __half* th, int K, int N, int i)
{
    int n = i / K, k = i % K;
    th[i] = __float2half_rn(W[(size_t)k * N + n]);
}

__global__ void prep_kernel(const float* nw0, const float* nw1,
                            const float* g1ws, const float* g1wd,
                            const float* g2ws, const float* g2wd,
                            const float* ew0, const float* ew1,
                            const float* g1bs, const float* g1bd,
                            const float* g2bs, const float* g2bd,
                            __half* nw0h, __half* nw1h,
                            __half* g1h, __half* g2h,
                            __half* w0h, __half* w1h,
                            float* b1c, float* b2c)
{
    int i = blockIdx.x * blockDim.x + threadIdx.x;
    if (i < 8192) { split_at(nw0, nw0h, 64, 128, i); return; }
    i -= 8192;
    if (i < 16384) { split_at(nw1, nw1h, 128, 128, i); return; }
    i -= 16384;
    if (i < 16384) { split_at(g1ws, g1h, 64, 256, i); return; }
    i -= 16384;
    if (i < 16384) { split_at(g1wd, g1h + 16384, 64, 256, i); return; }
    i -= 16384;
    if (i < 65536) { split_at(g2ws, g2h, 256, 256, i); return; }
    i -= 65536;
    if (i < 65536) { split_at(g2wd, g2h + 65536, 256, 256, i); return; }
    i -= 65536;
    if (i < 196608) {
        int n = i / 384, k = i % 384;
        int rs = (k < 128) ? k : k + 128;
        int rd = (k < 128) ? k + 128 : k + 384;
        w0h[i] = __float2half_rn(ew0[rs * 512 + n]);
        w0h[196608 + i] = __float2half_rn(ew0[rd * 512 + n]);
        return;
    }
    i -= 196608;
    if (i < 131072) { split_at(ew1, w1h, 512, 256, i); return; }
    i -= 131072;
    if (i < 512) { b1c[i] = (i < 256) ? g1bs[i] : g1bd[i - 256]; return; }
    i -= 512;
    if (i < 512) { b2c[i] = (i < 256) ? g2bs[i] : g2bd[i - 256]; return; }
}

// ---------------- host launch (round-14 fork-join + CSR on side) ----------------
extern "C" void kernel_launch(void* const* d_in, const int* in_sizes, int n_in,
                              void* d_out, int out_size)
{
    const float* x    = (const float*)d_in[0];
    const int*   src  = (const int*)d_in[1];
    const int*   dst  = (const int*)d_in[2];
    const float* nw0  = (const float*)d_in[3];
    const float* nb0  = (const float*)d_in[4];
    const float* nw1  = (const float*)d_in[5];
    const float* nb1  = (const float*)d_in[6];
    const float* g1ws = (const float*)d_in[7];
    const float* g1bs = (const float*)d_in[8];
    const float* g1wd = (const float*)d_in[9];
    const float* g1bd = (const float*)d_in[10];
    const float* g1a  = (const float*)d_in[11];
    const float* g2ws = (const float*)d_in[12];
    const float* g2bs = (const float*)d_in[13];
    const float* g2wd = (const float*)d_in[14];
    const float* g2bd = (const float*)d_in[15];
    const float* g2a  = (const float*)d_in[16];
    const float* ew0  = (const float*)d_in[17];
    const float* eb0  = (const float*)d_in[18];
    const float* ew1  = (const float*)d_in[19];
    const float* eb1  = (const float*)d_in[20];
    const float* ew2  = (const float*)d_in[21];
    const float* eb2  = (const float*)d_in[22];
    float* out = (float*)d_out;

    float *tmp, *h1, *acc, *sB, *acc2, *s2B, *b1c, *b2c;
    __half *fsd, *P;
    __half *nw0h, *nw1h, *g1h, *g2h, *w0h, *w1h;
    int *cnt, *cursor, *esrc, *edst, *eidx;
    cudaGetSymbolAddress((void**)&tmp,    g_tmp);
    cudaGetSymbolAddress((void**)&h1,     g_h1);
    cudaGetSymbolAddress((void**)&fsd,    g_fsd);
    cudaGetSymbolAddress((void**)&acc,    g_acc);
    cudaGetSymbolAddress((void**)&sB,     g_s);
    cudaGetSymbolAddress((void**)&acc2,   g_acc2);
    cudaGetSymbolAddress((void**)&s2B,    g_s2);
    cudaGetSymbolAddress((void**)&P,      g_p);
    cudaGetSymbolAddress((void**)&b1c,    g_b1cat);
    cudaGetSymbolAddress((void**)&b2c,    g_b2cat);
    cudaGetSymbolAddress((void**)&nw0h,   g_nw0h);
    cudaGetSymbolAddress((void**)&nw1h,   g_nw1h);
    cudaGetSymbolAddress((void**)&g1h,    g_g1h);
    cudaGetSymbolAddress((void**)&g2h,    g_g2h);
    cudaGetSymbolAddress((void**)&w0h,    g_w0h);
    cudaGetSymbolAddress((void**)&w1h,    g_w1h);
    cudaGetSymbolAddress((void**)&cnt,    g_cnt);
    cudaGetSymbolAddress((void**)&cursor, g_cursor);
    cudaGetSymbolAddress((void**)&esrc,   g_esrc);
    cudaGetSymbolAddress((void**)&edst,   g_edst);
    cudaGetSymbolAddress((void**)&eidx,   g_eidx);

    cudaFuncSetAttribute(mma_gemm_kernel, cudaFuncAttributeMaxDynamicSharedMemorySize, 40960);
    cudaFuncSetAttribute(edge_mma_kernel, cudaFuncAttributeMaxDynamicSharedMemorySize, 61440);

    cudaStream_t s2;
    cudaEvent_t eFork, eMs, eJoin;
    cudaStreamCreateWithFlags(&s2, cudaStreamNonBlocking);
    cudaEventCreateWithFlags(&eFork, cudaEventDisableTiming);
    cudaEventCreateWithFlags(&eMs,   cudaEventDisableTiming);
    cudaEventCreateWithFlags(&eJoin, cudaEventDisableTiming);

    const int MBY = (N_NODES + 127) / 128;   // 157

    // main: prep, then fork
    prep_kernel<<<(517120 + 255) / 256, 256>>>(
        nw0, nw1, g1ws, g1wd, g2ws, g2wd, ew0, ew1,
        g1bs, g1bd, g2bs, g2bd,
        nw0h, nw1h, g1h, g2h, w0h, w1h, b1c, b2c);
    cudaEventRecord(eFork, 0);
    cudaStreamWaitEvent(s2, eFork, 0);

    // side stream: memsets -> CSR build -> NodeMLP
    cudaMemsetAsync(acc,  0, (size_t)N_NODES * 256 * sizeof(float), s2);
    cudaMemsetAsync(sB,   0, (size_t)N_NODES * 2 * sizeof(float), s2);
    cudaMemsetAsync(acc2, 0, (size_t)N_NODES * 256 * sizeof(float), s2);
    cudaMemsetAsync(s2B,  0, (size_t)N_NODES * 2 * sizeof(float), s2);
    cudaMemsetAsync(cnt,  0, N_NODES * sizeof(int), s2);
    cudaEventRecord(eMs, s2);
    csr_hist_kernel<<<(N_EDGES + 255) / 256, 256, 0, s2>>>(dst, cnt);
    csr_scan_kernel<<<1, 1024, 0, s2>>>(cnt, cursor);
    csr_fill_kernel<<<(N_EDGES + 255) / 256, 256, 0, s2>>>(src, dst, cursor, esrc, edst, eidx);
    mma_gemm_kernel<<<dim3(1, MBY), 512, 40960, s2>>>(
        x, N_NODES, 64, nullptr, nw0h, nb0, 0, 1, nullptr, tmp, nullptr, 128);
    mma_gemm_kernel<<<dim3(1, MBY), 512, 40960, s2>>>(
        tmp, N_NODES, 128, nullptr, nw1h, nb1, 0, 1, nullptr, h1, nullptr, 128);
    cudaEventRecord(eJoin, s2);

    // main: GAT critical chain
    mma_gemm_kernel<<<dim3(4, MBY), 512, 40960>>>(
        x, N_NODES, 64, nullptr, g1h, b1c, 0, 0, nullptr, nullptr, fsd, 512);
    cudaStreamWaitEvent(0, eMs, 0);
    gat_fused_kernel<<<N_EDGES / 8, 256>>>(fsd, g1a, src, dst, sB, acc);

    mma_gemm_kernel<<<dim3(4, MBY), 512, 40960>>>(
        acc, N_NODES, 256, nullptr, g2h, b2c, 1, 0, sB, nullptr, fsd, 512);
    gat_fused_kernel<<<N_EDGES / 8, 256>>>(fsd, g2a, src, dst, s2B, acc2);

    // join: P-GEMM (single, K=384) needs h1 (side) + acc2/s2B (main)
    cudaStreamWaitEvent(0, eJoin, 0);
    mma_gemm_kernel<<<dim3(8, MBY), 512, 40960>>>(
        h1, N_NODES, 384, acc2, w0h, nullptr, 0, 0, s2B, nullptr, P, 1024);

    // EdgeMLP fused, dst-sorted edge order (also behind eJoin for CSR arrays)
    edge_mma_kernel<<<N_EDGES / 128, 512, 61440>>>(
        P, esrc, edst, eidx, eb0, w1h, eb1, ew2, eb2, out);

    cudaStreamDestroy(s2);
    cudaEventDestroy(eFork);
    cudaEventDestroy(eMs);
    cudaEventDestroy(eJoin);
}